// round 1
// baseline (speedup 1.0000x reference)
#include <cuda_runtime.h>
#include <math.h>

#define N_GENES 15135
#define BS 8
#define HID 64
#define NCMT 1000
#define HFC 128
#define NROWS (N_GENES * BS)       // 121080
#define FPN (BS * HID)             // 512 floats per node
#define E_MAX 262144

// ------------------- scratch (static device globals; no runtime alloc) -----
__device__ float g_h [(size_t)N_GENES * FPN];
__device__ float g_x1[(size_t)N_GENES * FPN];
__device__ float g_x2[(size_t)N_GENES * FPN];
__device__ float g_x3[(size_t)N_GENES * FPN];
__device__ float g_dinv[N_GENES];
__device__ int   g_cnt [N_GENES];
__device__ int   g_fill[N_GENES];
__device__ int   g_rowptr[N_GENES + 1];
__device__ int   g_csr_src [E_MAX];
__device__ float g_csr_norm[E_MAX];
__device__ float g_s[(size_t)NROWS];          // s[n*8+b]
__device__ float g_psum[NCMT * BS];           // psum[c*8+b]
__device__ float g_pcnt[NCMT];
__device__ float g_hidden[BS * HFC];

// ------------------- setup kernels ------------------------------------------
__global__ void zero_kernel() {
    int i = blockIdx.x * blockDim.x + threadIdx.x;
    if (i < N_GENES) { g_cnt[i] = 0; g_fill[i] = 0; }
    if (i < NCMT * BS) g_psum[i] = 0.f;
    if (i < NCMT) g_pcnt[i] = 0.f;
}

__global__ void degree_kernel(const int* __restrict__ ei, int E) {
    int e = blockIdx.x * blockDim.x + threadIdx.x;
    if (e >= E) return;
    int dst = ei[E + e];
    atomicAdd(&g_cnt[dst], 1);
}

// single block: dinv + exclusive prefix of cnt -> rowptr
__global__ void scan_kernel() {
    __shared__ int sh[1024];
    int tid = threadIdx.x;
    int carry = 0;
    for (int base = 0; base < N_GENES; base += 1024) {
        int i = base + tid;
        int v = (i < N_GENES) ? g_cnt[i] : 0;
        if (i < N_GENES) g_dinv[i] = rsqrtf((float)v + 1.0f);
        __syncthreads();           // protect prior sh[1023] reads
        sh[tid] = v;
        __syncthreads();
        for (int off = 1; off < 1024; off <<= 1) {
            int t = (tid >= off) ? sh[tid - off] : 0;
            __syncthreads();
            sh[tid] += t;
            __syncthreads();
        }
        if (i < N_GENES) g_rowptr[i] = carry + sh[tid] - v;  // exclusive
        carry += sh[1023];
    }
    if (tid == 0) g_rowptr[N_GENES] = carry;
}

__global__ void fill_kernel(const int* __restrict__ ei, int E) {
    int e = blockIdx.x * blockDim.x + threadIdx.x;
    if (e >= E) return;
    int src = ei[e];
    int dst = ei[E + e];
    int pos = g_rowptr[dst] + atomicAdd(&g_fill[dst], 1);
    g_csr_src[pos] = src;
    g_csr_norm[pos] = g_dinv[src] * g_dinv[dst];
}

// ------------------- GEMM: out[r*64+f] = sum_k in_row(r)[k] * W[k*64+f] ----
// layout==0: input is x [bs, N, 64], row r -> (n=r>>3, b=r&7)
// layout==1: input is [N, bs, 64] flat, row r contiguous
__global__ void gemm_kernel(const float* __restrict__ in, const float* __restrict__ W,
                            float* __restrict__ out, int layout) {
    __shared__ float sW[64 * 64];
    __shared__ float sIn[32 * 64];
    int tid = threadIdx.x;                       // 256 threads
    for (int i = tid; i < 4096; i += 256) sW[i] = W[i];
    __syncthreads();
    float wcol[64];
    int f = tid & 63;
#pragma unroll
    for (int k = 0; k < 64; k++) wcol[k] = sW[k * 64 + f];
    int rlane = tid >> 6;                        // 0..3
    int rbase = blockIdx.x * 256;
    for (int tile = 0; tile < 8; tile++) {
        int trow0 = rbase + tile * 32;
        __syncthreads();
        // cooperative load of 32 rows (512 float4's)
        for (int i = tid; i < 512; i += 256) {
            int rr = i >> 4, c4 = i & 15;
            int grow = trow0 + rr;
            float4 v = make_float4(0.f, 0.f, 0.f, 0.f);
            if (grow < NROWS) {
                const float* src;
                if (layout == 0) {
                    int nn = grow >> 3, bb = grow & 7;
                    src = in + ((size_t)bb * N_GENES + nn) * 64;
                } else {
                    src = in + (size_t)grow * 64;
                }
                v = ((const float4*)src)[c4];
            }
            ((float4*)sIn)[i] = v;
        }
        __syncthreads();
#pragma unroll
        for (int j = 0; j < 8; j++) {
            int rr = rlane + j * 4;
            int grow = trow0 + rr;
            float acc = 0.f;
            const float4* rp = (const float4*)(sIn + rr * 64);
#pragma unroll
            for (int k4 = 0; k4 < 16; k4++) {
                float4 v = rp[k4];
                acc += v.x * wcol[4 * k4] + v.y * wcol[4 * k4 + 1]
                     + v.z * wcol[4 * k4 + 2] + v.w * wcol[4 * k4 + 3];
            }
            if (grow < NROWS) out[(size_t)grow * 64 + f] = acc;
        }
    }
}

// ------------------- GCN aggregate: xout[n] = relu(sum_e w*h[src] + dinv^2*h[n] + b)
__global__ void agg_kernel(const float* __restrict__ h, const float* __restrict__ b,
                           float* __restrict__ xout) {
    int n = blockIdx.x;
    int t = threadIdx.x;                          // 0..127, float4 lanes
    const float4* h4 = (const float4*)h;
    float dv = g_dinv[n];
    float4 acc = h4[(size_t)n * 128 + t];
    float w0 = dv * dv;
    acc.x *= w0; acc.y *= w0; acc.z *= w0; acc.w *= w0;
    int e0 = g_rowptr[n], e1 = g_rowptr[n + 1];
    for (int e = e0; e < e1; e++) {
        int s = g_csr_src[e];
        float w = g_csr_norm[e];
        float4 v = h4[(size_t)s * 128 + t];
        acc.x += w * v.x; acc.y += w * v.y; acc.z += w * v.z; acc.w += w * v.w;
    }
    int c = t * 4;
    acc.x += b[c & 63]; acc.y += b[(c + 1) & 63]; acc.z += b[(c + 2) & 63]; acc.w += b[(c + 3) & 63];
    acc.x = fmaxf(acc.x, 0.f); acc.y = fmaxf(acc.y, 0.f);
    acc.z = fmaxf(acc.z, 0.f); acc.w = fmaxf(acc.w, 0.f);
    ((float4*)xout)[(size_t)n * 128 + t] = acc;
}

// ------------------- s[r] = sum_h x1[r,h]*fcW[3h] + x2*fcW[3h+1] + x3*fcW[3h+2]
__global__ void s_kernel(const float* __restrict__ fcW) {
    int gtid = blockIdx.x * blockDim.x + threadIdx.x;
    int warp = gtid >> 5;
    int lane = threadIdx.x & 31;
    if (warp >= NROWS) return;
    size_t base = (size_t)warp * 64;
    float a = g_x1[base + lane] * fcW[3 * lane]
            + g_x2[base + lane] * fcW[3 * lane + 1]
            + g_x3[base + lane] * fcW[3 * lane + 2];
    int l2 = lane + 32;
    a += g_x1[base + l2] * fcW[3 * l2]
       + g_x2[base + l2] * fcW[3 * l2 + 1]
       + g_x3[base + l2] * fcW[3 * l2 + 2];
#pragma unroll
    for (int off = 16; off; off >>= 1) a += __shfl_xor_sync(0xffffffffu, a, off);
    if (lane == 0) g_s[warp] = a;
}

// ------------------- pathway segment-sum of s --------------------------------
__global__ void seg_kernel(const int* __restrict__ prow, const int* __restrict__ pcol, int P) {
    int tid = blockIdx.x * blockDim.x + threadIdx.x;
    if (tid >= P * BS) return;
    int p = tid >> 3, b = tid & 7;
    int c = pcol[p], r = prow[p];
    atomicAdd(&g_psum[c * 8 + b], g_s[(size_t)r * 8 + b]);
    if (b == 0) atomicAdd(&g_pcnt[c], 1.0f);
}

// ------------------- MLP head ------------------------------------------------
__global__ void mlp1_kernel(const float* __restrict__ l1W, const float* __restrict__ l1b,
                            const float* __restrict__ fcb) {
    __shared__ float h0[NCMT];
    int b = blockIdx.x, j = threadIdx.x;          // 128 threads
    float fb = fcb[0];
    for (int c = j; c < NCMT; c += 128) {
        float cnt = g_pcnt[c];
        cnt = cnt > 1.f ? cnt : 1.f;
        h0[c] = g_psum[c * 8 + b] / cnt + fb;
    }
    __syncthreads();
    float acc = l1b[j];
    for (int c = 0; c < NCMT; c++) acc += h0[c] * l1W[c * HFC + j];
    g_hidden[b * HFC + j] = fmaxf(acc, 0.f);
}

__global__ void mlp2_kernel(const float* __restrict__ l2W, const float* __restrict__ l2b,
                            float* __restrict__ out) {
    int b = threadIdx.x;
    if (b >= BS) return;
    float z0 = l2b[0], z1 = l2b[1];
#pragma unroll 4
    for (int j = 0; j < HFC; j++) {
        float hv = g_hidden[b * HFC + j];
        z0 += hv * l2W[j * 2];
        z1 += hv * l2W[j * 2 + 1];
    }
    float m = fmaxf(z0, z1);
    float lse = m + logf(expf(z0 - m) + expf(z1 - m));
    out[b * 2]     = z0 - lse;
    out[b * 2 + 1] = z1 - lse;
}

// ------------------- launch --------------------------------------------------
extern "C" void kernel_launch(void* const* d_in, const int* in_sizes, int n_in,
                              void* d_out, int out_size) {
    const float* x    = (const float*)d_in[0];
    const int*   ei   = (const int*)  d_in[2];
    const int*   prow = (const int*)  d_in[3];
    const int*   pcol = (const int*)  d_in[4];
    const float* W1   = (const float*)d_in[5];
    const float* b1   = (const float*)d_in[6];
    const float* W2   = (const float*)d_in[7];
    const float* b2   = (const float*)d_in[8];
    const float* W3   = (const float*)d_in[9];
    const float* b3   = (const float*)d_in[10];
    const float* fcW  = (const float*)d_in[11];
    const float* fcb  = (const float*)d_in[12];
    const float* l1W  = (const float*)d_in[13];
    const float* l1b  = (const float*)d_in[14];
    const float* l2W  = (const float*)d_in[15];
    const float* l2b  = (const float*)d_in[16];
    float* out = (float*)d_out;

    int E = in_sizes[2] / 2;
    int P = in_sizes[3];

    zero_kernel<<<(N_GENES + 255) / 256, 256>>>();
    degree_kernel<<<(E + 255) / 256, 256>>>(ei, E);
    scan_kernel<<<1, 1024>>>();
    fill_kernel<<<(E + 255) / 256, 256>>>(ei, E);

    int gemm_blocks = (NROWS + 255) / 256;

    gemm_kernel<<<gemm_blocks, 256>>>(x, W1, g_h, 0);
    agg_kernel<<<N_GENES, 128>>>(g_h, b1, g_x1);

    gemm_kernel<<<gemm_blocks, 256>>>(g_x1, W2, g_h, 1);
    agg_kernel<<<N_GENES, 128>>>(g_h, b2, g_x2);

    gemm_kernel<<<gemm_blocks, 256>>>(g_x2, W3, g_h, 1);
    agg_kernel<<<N_GENES, 128>>>(g_h, b3, g_x3);

    s_kernel<<<(NROWS * 32 + 255) / 256, 256>>>(fcW);
    seg_kernel<<<(P * BS + 255) / 256, 256>>>(prow, pcol, P);
    mlp1_kernel<<<BS, HFC>>>(l1W, l1b, fcb);
    mlp2_kernel<<<1, 32>>>(l2W, l2b, out);
}

// round 3
// speedup vs baseline: 1.0545x; 1.0545x over previous
#include <cuda_runtime.h>
#include <math.h>

#define N_GENES 15135
#define BS 8
#define HID 64
#define NCMT 1000
#define HFC 128
#define NROWS (N_GENES * BS)       // 121080
#define FPN (BS * HID)             // 512 floats per node
#define E_MAX 262144
#define P_MAX 131072

// ------------------- scratch (static device globals; no runtime alloc) -----
__device__ float g_h [(size_t)N_GENES * FPN];
__device__ float g_x1[(size_t)N_GENES * FPN];
__device__ float g_x2[(size_t)N_GENES * FPN];
__device__ float g_x3[(size_t)N_GENES * FPN];
__device__ float g_dinv[N_GENES];
__device__ int   g_cnt [N_GENES];
__device__ int   g_fill[N_GENES];
__device__ int   g_rowptr[N_GENES + 1];
__device__ int   g_csr_src [E_MAX];
__device__ float g_csr_norm[E_MAX];
// pathway CSR (segments = communities/cols)
__device__ int   g_cnt2 [NCMT];
__device__ int   g_fill2[NCMT];
__device__ int   g_rowptr2[NCMT + 1];
__device__ int   g_csr2_row[P_MAX];
__device__ float g_s[(size_t)NROWS];          // s[n*8+b]
__device__ float g_pool[NCMT * BS];           // pooled mean + fcb, [c*8+b]
__device__ float g_hidden[BS * HFC];

// ------------------- setup kernels ------------------------------------------
__global__ void zero_kernel() {
    int i = blockIdx.x * blockDim.x + threadIdx.x;
    if (i < N_GENES) { g_cnt[i] = 0; g_fill[i] = 0; }
    if (i < NCMT)    { g_cnt2[i] = 0; g_fill2[i] = 0; }
}

__global__ void degree_kernel(const int* __restrict__ ei, int E) {
    int e = blockIdx.x * blockDim.x + threadIdx.x;
    if (e >= E) return;
    atomicAdd(&g_cnt[ei[E + e]], 1);
}

__global__ void degree2_kernel(const int* __restrict__ pcol, int P) {
    int p = blockIdx.x * blockDim.x + threadIdx.x;
    if (p >= P) return;
    atomicAdd(&g_cnt2[pcol[p]], 1);
}

// single block: dinv + exclusive prefix of cnt -> rowptr (genes)
__global__ void scan_kernel() {
    __shared__ int sh[1024];
    int tid = threadIdx.x;
    int carry = 0;
    for (int base = 0; base < N_GENES; base += 1024) {
        int i = base + tid;
        int v = (i < N_GENES) ? g_cnt[i] : 0;
        if (i < N_GENES) g_dinv[i] = 1.0f / sqrtf((float)v + 1.0f);
        __syncthreads();
        sh[tid] = v;
        __syncthreads();
        for (int off = 1; off < 1024; off <<= 1) {
            int t = (tid >= off) ? sh[tid - off] : 0;
            __syncthreads();
            sh[tid] += t;
            __syncthreads();
        }
        if (i < N_GENES) g_rowptr[i] = carry + sh[tid] - v;  // exclusive
        carry += sh[1023];
    }
    if (tid == 0) g_rowptr[N_GENES] = carry;
}

// single block: exclusive prefix of cnt2 -> rowptr2 (1000 entries)
__global__ void scan2_kernel() {
    __shared__ int sh[1024];
    int tid = threadIdx.x;
    int v = (tid < NCMT) ? g_cnt2[tid] : 0;
    sh[tid] = v;
    __syncthreads();
    for (int off = 1; off < 1024; off <<= 1) {
        int t = (tid >= off) ? sh[tid - off] : 0;
        __syncthreads();
        sh[tid] += t;
        __syncthreads();
    }
    if (tid < NCMT) g_rowptr2[tid] = sh[tid] - v;
    if (tid == NCMT - 1) g_rowptr2[NCMT] = sh[tid];
}

__global__ void fill_kernel(const int* __restrict__ ei, int E) {
    int e = blockIdx.x * blockDim.x + threadIdx.x;
    if (e >= E) return;
    int src = ei[e];
    int dst = ei[E + e];
    int pos = g_rowptr[dst] + atomicAdd(&g_fill[dst], 1);
    g_csr_src[pos] = src;
    g_csr_norm[pos] = g_dinv[src] * g_dinv[dst];
}

__global__ void fill2_kernel(const int* __restrict__ prow, const int* __restrict__ pcol, int P) {
    int p = blockIdx.x * blockDim.x + threadIdx.x;
    if (p >= P) return;
    int c = pcol[p];
    int pos = g_rowptr2[c] + atomicAdd(&g_fill2[c], 1);
    g_csr2_row[pos] = prow[p];
}

// ------------------- GEMM: out[r*64+f] = sum_k in_row(r)[k] * W[k*64+f] ----
// layout==0: input is x [bs, N, 64], row r -> (n=r>>3, b=r&7)
// layout==1: input is [N, bs, 64] flat, row r contiguous
__global__ void __launch_bounds__(256) gemm_kernel(
        const float* __restrict__ in, const float* __restrict__ W,
        float* __restrict__ out, int layout) {
    __shared__ float sW[64 * 64];
    __shared__ float sIn[32 * 64];
    int tid = threadIdx.x;                       // 256 threads
    for (int i = tid; i < 4096; i += 256) sW[i] = W[i];
    __syncthreads();
    float wcol[64];
    int f = tid & 63;
#pragma unroll
    for (int k = 0; k < 64; k++) wcol[k] = sW[k * 64 + f];
    int rlane = tid >> 6;                        // 0..3
    int rbase = blockIdx.x * 256;
    for (int tile = 0; tile < 8; tile++) {
        int trow0 = rbase + tile * 32;
        __syncthreads();
        for (int i = tid; i < 512; i += 256) {
            int rr = i >> 4, c4 = i & 15;
            int grow = trow0 + rr;
            float4 v = make_float4(0.f, 0.f, 0.f, 0.f);
            if (grow < NROWS) {
                const float* src;
                if (layout == 0) {
                    int nn = grow >> 3, bb = grow & 7;
                    src = in + ((size_t)bb * N_GENES + nn) * 64;
                } else {
                    src = in + (size_t)grow * 64;
                }
                v = ((const float4*)src)[c4];
            }
            ((float4*)sIn)[i] = v;
        }
        __syncthreads();
#pragma unroll
        for (int j = 0; j < 8; j++) {
            int rr = rlane + j * 4;
            int grow = trow0 + rr;
            float acc = 0.f;
            const float4* rp = (const float4*)(sIn + rr * 64);
#pragma unroll
            for (int k4 = 0; k4 < 16; k4++) {
                float4 v = rp[k4];
                acc += v.x * wcol[4 * k4] + v.y * wcol[4 * k4 + 1]
                     + v.z * wcol[4 * k4 + 2] + v.w * wcol[4 * k4 + 3];
            }
            if (grow < NROWS) out[(size_t)grow * 64 + f] = acc;
        }
    }
}

// ------------------- GCN aggregate: xout[n] = relu(sum_e w*h[src] + dinv^2*h[n] + b)
__global__ void __launch_bounds__(128) agg_kernel(
        const float* __restrict__ h, const float* __restrict__ b,
        float* __restrict__ xout) {
    int n = blockIdx.x;
    int t = threadIdx.x;                          // 0..127, float4 lanes
    const float4* __restrict__ h4 = (const float4*)h;
    float dv = g_dinv[n];
    float4 acc = h4[(size_t)n * 128 + t];
    float w0 = dv * dv;
    acc.x *= w0; acc.y *= w0; acc.z *= w0; acc.w *= w0;
    int e0 = g_rowptr[n], e1 = g_rowptr[n + 1];
    int e = e0;
    for (; e + 4 <= e1; e += 4) {
        int s0 = g_csr_src[e], s1 = g_csr_src[e + 1];
        int s2 = g_csr_src[e + 2], s3 = g_csr_src[e + 3];
        float w0_ = g_csr_norm[e],     w1_ = g_csr_norm[e + 1];
        float w2_ = g_csr_norm[e + 2], w3_ = g_csr_norm[e + 3];
        float4 v0 = h4[(size_t)s0 * 128 + t];
        float4 v1 = h4[(size_t)s1 * 128 + t];
        float4 v2 = h4[(size_t)s2 * 128 + t];
        float4 v3 = h4[(size_t)s3 * 128 + t];
        acc.x += w0_ * v0.x; acc.y += w0_ * v0.y; acc.z += w0_ * v0.z; acc.w += w0_ * v0.w;
        acc.x += w1_ * v1.x; acc.y += w1_ * v1.y; acc.z += w1_ * v1.z; acc.w += w1_ * v1.w;
        acc.x += w2_ * v2.x; acc.y += w2_ * v2.y; acc.z += w2_ * v2.z; acc.w += w2_ * v2.w;
        acc.x += w3_ * v3.x; acc.y += w3_ * v3.y; acc.z += w3_ * v3.z; acc.w += w3_ * v3.w;
    }
    for (; e < e1; e++) {
        int s = g_csr_src[e];
        float w = g_csr_norm[e];
        float4 v = h4[(size_t)s * 128 + t];
        acc.x += w * v.x; acc.y += w * v.y; acc.z += w * v.z; acc.w += w * v.w;
    }
    float4 bb = ((const float4*)b)[t & 15];
    acc.x = fmaxf(acc.x + bb.x, 0.f);
    acc.y = fmaxf(acc.y + bb.y, 0.f);
    acc.z = fmaxf(acc.z + bb.z, 0.f);
    acc.w = fmaxf(acc.w + bb.w, 0.f);
    ((float4*)xout)[(size_t)n * 128 + t] = acc;
}

// ------------------- s[r] = sum_h x1[r,h]*fcW[3h] + x2*fcW[3h+1] + x3*fcW[3h+2]
__global__ void s_kernel(const float* __restrict__ fcW) {
    int gtid = blockIdx.x * blockDim.x + threadIdx.x;
    int warp = gtid >> 5;
    int lane = threadIdx.x & 31;
    if (warp >= NROWS) return;
    size_t base = (size_t)warp * 64;
    float a = g_x1[base + lane] * fcW[3 * lane]
            + g_x2[base + lane] * fcW[3 * lane + 1]
            + g_x3[base + lane] * fcW[3 * lane + 2];
    int l2 = lane + 32;
    a += g_x1[base + l2] * fcW[3 * l2]
       + g_x2[base + l2] * fcW[3 * l2 + 1]
       + g_x3[base + l2] * fcW[3 * l2 + 2];
#pragma unroll
    for (int off = 16; off; off >>= 1) a += __shfl_xor_sync(0xffffffffu, a, off);
    if (lane == 0) g_s[warp] = a;
}

// ------------------- pathway pooled mean via CSR (deterministic, double) ----
// block = community c; 256 threads = 32 entry-lanes x 8 batch-lanes
__global__ void __launch_bounds__(256) pool_kernel(const float* __restrict__ fcb) {
    __shared__ double sh[256];
    int c = blockIdx.x;
    int tid = threadIdx.x;
    int b = tid & 7;          // batch lane
    int i = tid >> 3;         // entry lane 0..31
    int e0 = g_rowptr2[c], e1 = g_rowptr2[c + 1];
    double acc = 0.0;
    for (int e = e0 + i; e < e1; e += 32) {
        int r = g_csr2_row[e];
        acc += (double)g_s[(size_t)r * 8 + b];
    }
    sh[tid] = acc;
    __syncthreads();
    for (int off = 128; off >= 8; off >>= 1) {
        if (tid < off) sh[tid] += sh[tid + off];
        __syncthreads();
    }
    if (tid < 8) {
        double cnt = (double)(e1 - e0);
        if (cnt < 1.0) cnt = 1.0;
        g_pool[c * 8 + tid] = (float)(sh[tid] / cnt + (double)fcb[0]);
    }
}

// ------------------- MLP head (double accumulation) --------------------------
__global__ void mlp1_kernel(const float* __restrict__ l1W, const float* __restrict__ l1b) {
    int b = blockIdx.x, j = threadIdx.x;          // 128 threads
    double acc = (double)l1b[j];
    for (int c = 0; c < NCMT; c++)
        acc += (double)g_pool[c * 8 + b] * (double)l1W[c * HFC + j];
    float v = (float)acc;
    g_hidden[b * HFC + j] = fmaxf(v, 0.f);
}

__global__ void mlp2_kernel(const float* __restrict__ l2W, const float* __restrict__ l2b,
                            float* __restrict__ out) {
    int b = threadIdx.x;
    if (b >= BS) return;
    double z0 = (double)l2b[0], z1 = (double)l2b[1];
    for (int j = 0; j < HFC; j++) {
        double hv = (double)g_hidden[b * HFC + j];
        z0 += hv * (double)l2W[j * 2];
        z1 += hv * (double)l2W[j * 2 + 1];
    }
    double m = z0 > z1 ? z0 : z1;
    double lse = m + log(exp(z0 - m) + exp(z1 - m));
    out[b * 2]     = (float)(z0 - lse);
    out[b * 2 + 1] = (float)(z1 - lse);
}

// ------------------- launch --------------------------------------------------
extern "C" void kernel_launch(void* const* d_in, const int* in_sizes, int n_in,
                              void* d_out, int out_size) {
    const float* x    = (const float*)d_in[0];
    const int*   ei   = (const int*)  d_in[2];
    const int*   prow = (const int*)  d_in[3];
    const int*   pcol = (const int*)  d_in[4];
    const float* W1   = (const float*)d_in[5];
    const float* b1   = (const float*)d_in[6];
    const float* W2   = (const float*)d_in[7];
    const float* b2   = (const float*)d_in[8];
    const float* W3   = (const float*)d_in[9];
    const float* b3   = (const float*)d_in[10];
    const float* fcW  = (const float*)d_in[11];
    const float* fcb  = (const float*)d_in[12];
    const float* l1W  = (const float*)d_in[13];
    const float* l1b  = (const float*)d_in[14];
    const float* l2W  = (const float*)d_in[15];
    const float* l2b  = (const float*)d_in[16];
    float* out = (float*)d_out;

    int E = in_sizes[2] / 2;
    int P = in_sizes[3];

    zero_kernel<<<(N_GENES + 255) / 256, 256>>>();
    degree_kernel<<<(E + 255) / 256, 256>>>(ei, E);
    degree2_kernel<<<(P + 255) / 256, 256>>>(pcol, P);
    scan_kernel<<<1, 1024>>>();
    scan2_kernel<<<1, 1024>>>();
    fill_kernel<<<(E + 255) / 256, 256>>>(ei, E);
    fill2_kernel<<<(P + 255) / 256, 256>>>(prow, pcol, P);

    int gemm_blocks = (NROWS + 255) / 256;

    gemm_kernel<<<gemm_blocks, 256>>>(x, W1, g_h, 0);
    agg_kernel<<<N_GENES, 128>>>(g_h, b1, g_x1);

    gemm_kernel<<<gemm_blocks, 256>>>(g_x1, W2, g_h, 1);
    agg_kernel<<<N_GENES, 128>>>(g_h, b2, g_x2);

    gemm_kernel<<<gemm_blocks, 256>>>(g_x2, W3, g_h, 1);
    agg_kernel<<<N_GENES, 128>>>(g_h, b3, g_x3);

    s_kernel<<<(NROWS * 32 + 255) / 256, 256>>>(fcW);
    pool_kernel<<<NCMT, 256>>>(fcb);
    mlp1_kernel<<<BS, HFC>>>(l1W, l1b);
    mlp2_kernel<<<1, 32>>>(l2W, l2b, out);
}